// round 10
// baseline (speedup 1.0000x reference)
#include <cuda_runtime.h>
#include <math.h>

#define LL 256
#define MAXB 512
#define NBLK 592          // 4 blocks/SM x 148 SMs: exactly one balanced wave
#define UROWS 8           // rows per unit
#define UV4 512           // float4 per unit (8 rows * 64)

// ---- per-sample accumulators (zero-init; finalize kernel resets them) ----
__device__ float    g_sum [MAXB];     // sum(Yp)
__device__ float    g_gsum[MAXB];     // sum(Yg*Yp)
__device__ int      g_any [MAXB];     // any(Yg>0)
__device__ int      g_maxR1[MAXB];    // maxR+1 (0 = none)
__device__ int      g_minRi[MAXB];    // 256-minR (0 = none)
__device__ unsigned g_colb[MAXB][8];  // 256 column-flag bits
__device__ float    g_total;          // zero-init; reset by final block
__device__ int      g_nfin;           // zero-init; reset by final block

// =====================================================================
// Kernel A: balanced linear stream. 592 blocks, each owns a contiguous
// run of 8-row units; per-sample partials merged via global atomics.
// =====================================================================
__global__ void __launch_bounds__(512, 4)
k_stream(const float* __restrict__ Yp, const float* __restrict__ Yg, int NU)
{
    const int t = threadIdx.x;
    const int k = blockIdx.x;
    const int nb = gridDim.x;
    const int q = NU / nb, r = NU % nb;
    const int u0 = k * q + min(k, r);
    const int u1 = u0 + q + (k < r ? 1 : 0);

    const unsigned full = 0xffffffffu;
    const int warp = t >> 5, lane = t & 31;
    const float4* __restrict__ p4 = (const float4*)Yp;
    const float4* __restrict__ g4 = (const float4*)Yg;

    __shared__ float s1[16], s2[16], s3[16];
    __shared__ int   s4[16], s5[16];

    const int b0 = u0 >> 5;            // 32 units per sample
    const int b1 = (u1 - 1) >> 5;

    for (int b = b0; b <= b1; ++b) {   // at most 2 iterations
        const int uu0 = max(u0, b << 5);
        const int uu1 = min(u1, (b + 1) << 5);

        float sp = 0.f, spg = 0.f, gmax = 0.f;
        float cm0 = 0.f, cm1 = 0.f, cm2 = 0.f, cm3 = 0.f;
        int minR = LL, maxR = -1;

        #pragma unroll 4
        for (int u = uu0; u < uu1; ++u) {
            const int i = (u << 9) + t;       // global float4 index
            float4 v = p4[i];
            float4 g = g4[i];
            sp  += (v.x + v.y) + (v.z + v.w);
            spg += g.x * v.x + g.y * v.y + g.z * v.z + g.w * v.w;
            gmax = fmaxf(gmax, fmaxf(fmaxf(g.x, g.y), fmaxf(g.z, g.w)));
            cm0 = fmaxf(cm0, v.x); cm1 = fmaxf(cm1, v.y);
            cm2 = fmaxf(cm2, v.z); cm3 = fmaxf(cm3, v.w);
            float m = fmaxf(fmaxf(v.x, v.y), fmaxf(v.z, v.w));
            if (m > 0.5f) {                    // rare (blob rows only)
                int rr = (i >> 6) & 255;       // row within sample
                minR = min(minR, rr);
                maxR = max(maxR, rr);
            }
        }

        // rare per-thread column flags (columns fixed per thread: 4*(t&63)+s)
        unsigned cb = (cm0 > 0.5f ? 1u : 0u) | (cm1 > 0.5f ? 2u : 0u) |
                      (cm2 > 0.5f ? 4u : 0u) | (cm3 > 0.5f ? 8u : 0u);
        if (cb) atomicOr(&g_colb[b][(t & 63) >> 3], cb << (((t & 7)) << 2));

        // block reduction, then one set of atomics by thread 0
        #pragma unroll
        for (int o = 16; o > 0; o >>= 1) {
            sp   += __shfl_down_sync(full, sp, o);
            spg  += __shfl_down_sync(full, spg, o);
            gmax  = fmaxf(gmax, __shfl_down_sync(full, gmax, o));
            minR  = min(minR, __shfl_down_sync(full, minR, o));
            maxR  = max(maxR, __shfl_down_sync(full, maxR, o));
        }
        if (lane == 0) { s1[warp] = sp; s2[warp] = spg; s3[warp] = gmax;
                         s4[warp] = minR; s5[warp] = maxR; }
        __syncthreads();
        if (t == 0) {
            float a = 0.f, c = 0.f, gm = 0.f;
            int mnr = LL, mxr = -1;
            #pragma unroll
            for (int w = 0; w < 16; w++) {
                a += s1[w]; c += s2[w]; gm = fmaxf(gm, s3[w]);
                mnr = min(mnr, s4[w]); mxr = max(mxr, s5[w]);
            }
            atomicAdd(&g_sum[b],  a);
            atomicAdd(&g_gsum[b], c);
            if (gm > 0.f) atomicOr(&g_any[b], 1);
            if (mxr >= 0) {
                atomicMax(&g_maxR1[b], mxr + 1);
                atomicMax(&g_minRi[b], LL - mnr);
            }
        }
        __syncthreads();               // shared reuse across segments
    }
}

// =====================================================================
// Kernel B: per-sample finalize (box + window mask + ratio), global sum,
// final log, and slot reset for graph replay.
// =====================================================================
__global__ void __launch_bounds__(256)
k_final(const float* __restrict__ Yp, float* __restrict__ out, int B)
{
    const int b = blockIdx.x;
    const int t = threadIdx.x;
    const unsigned full = 0xffffffffu;
    const int warp = t >> 5, lane = t & 31;

    __shared__ float shSum, shPos, shAcc[8];
    __shared__ int   shAny, shGen, shC0, shR0, shW, shN;
    __shared__ float shGt0, shGt1, shXr, shYr;

    if (t == 0) {
        shSum = g_sum[b];
        shPos = g_gsum[b];
        int any = g_any[b];
        shAny = any;
        shGen = 0;
        if (!any) {
            int mxr1 = g_maxR1[b], mnri = g_minRi[b];
            int mnc = LL, mxc = -1;
            #pragma unroll
            for (int w = 0; w < 8; w++) {
                unsigned bits = g_colb[b][w];
                if (bits) {
                    mnc = min(mnc, (w << 5) + __ffs(bits) - 1);
                    mxc = max(mxc, (w << 5) + 31 - __clz(bits));
                }
            }
            int left, right, up, down;
            if (mxr1 == 0) { left = 0; right = 0; }
            else           { left = LL - mnri; right = (LL - 1) - (mxr1 - 1); }
            if (mxc < 0)   { up = 0; down = 0; }
            else           { up = mnc; down = (LL - 1) - mxc; }
            int x_r = (right - left) >> 1;    // floor div, matches //2
            int y_r = (down  - up)   >> 1;
            float gt0 = (float)(left + x_r);  // vs column coord
            float gt1 = (float)(up   + y_r);  // vs row coord
            if (x_r != 0 && y_r != 0) {
                // h>0.1 <=> d0^4+d1^4 < ln(10)*4/9 => |d0|,|d1| < ~1.006
                float hx = fabsf((float)x_r) * 1.01f + 1.5f;
                float hy = fabsf((float)y_r) * 1.01f + 1.5f;
                int c0 = max(0, (int)floorf(gt0 - hx));
                int c1 = min(LL - 1, (int)ceilf(gt0 + hx));
                int r0 = max(0, (int)floorf(gt1 - hy));
                int r1 = min(LL - 1, (int)ceilf(gt1 + hy));
                shC0 = c0; shR0 = r0;
                shW = c1 - c0 + 1;
                shN = (c1 - c0 + 1) * (r1 - r0 + 1);
                shXr = (float)x_r; shYr = (float)y_r;
                shGt0 = gt0; shGt1 = gt1;
                shGen = 1;
            }
        }
        // reset this sample's slots for next graph replay
        g_sum[b] = 0.f; g_gsum[b] = 0.f; g_any[b] = 0;
        g_maxR1[b] = 0; g_minRi[b] = 0;
        #pragma unroll
        for (int w = 0; w < 8; w++) g_colb[b][w] = 0u;
    }
    __syncthreads();

    float positive;
    if (shAny) {
        positive = shPos;
    } else if (!shGen) {
        positive = 0.f;                       // degenerate box -> empty mask
    } else {
        const float denom = 0.44444445f;      // f32((2/3)^2)
        const float* __restrict__ base = Yp + (size_t)b * (LL * LL);
        const int W = shW, n = shN, c0 = shC0, r0 = shR0;
        const float gt0 = shGt0, gt1 = shGt1, xr = shXr, yr = shYr;
        float acc = 0.f;
        for (int i = t; i < n; i += 256) {
            int rr = r0 + i / W;
            int cc = c0 + i % W;
            float d0 = ((float)cc - gt0) / xr;
            float d1 = ((float)rr - gt1) / yr;
            float d02 = d0 * d0, d12 = d1 * d1;
            float s = d02 * d02 + d12 * d12;
            float h = expf(-s / denom);
            if (h > 0.1f) acc += base[rr * LL + cc];
        }
        #pragma unroll
        for (int o = 16; o > 0; o >>= 1) acc += __shfl_down_sync(full, acc, o);
        if (lane == 0) shAcc[warp] = acc;
        __syncthreads();
        float tot = 0.f;
        if (t == 0) {
            #pragma unroll
            for (int w = 0; w < 8; w++) tot += shAcc[w];
        }
        positive = tot;                        // only thread 0's value used
    }

    if (t == 0) {
        float negative = shSum - positive;
        float ratio = negative / (positive + 1e-6f);
        atomicAdd(&g_total, ratio);
        __threadfence();
        int nfin = atomicAdd(&g_nfin, 1);
        if (nfin == B - 1) {
            float total = atomicExch(&g_total, 0.f);   // read + reset
            atomicExch(&g_nfin, 0);                    // reset
            out[0] = (total == 0.f) ? 0.f : (logf(total) / (float)B);
        }
    }
}

extern "C" void kernel_launch(void* const* d_in, const int* in_sizes, int n_in,
                              void* d_out, int out_size)
{
    const float* Yp = (const float*)d_in[0];
    const float* Yg = (const float*)d_in[1];
    int B = in_sizes[0] / (LL * LL);
    if (B > MAXB) B = MAXB;
    int NU = B * 32;                  // 8-row units total

    k_stream<<<NBLK, 512>>>(Yp, Yg, NU);
    k_final<<<B, 256>>>(Yp, (float*)d_out, B);
}